// round 14
// baseline (speedup 1.0000x reference)
#include <cuda_runtime.h>
#include <math_constants.h>

#define N     2048
#define NT    128
#define NCLS  10
#define C707  0.70710678118654752440f

typedef unsigned long long ull;

__device__ float2 g_cw1[N];   // exp(i*w1[n]), row-invariant

__global__ void vpc_init(const float* __restrict__ w) {
    int i = blockIdx.x * blockDim.x + threadIdx.x;
    if (i < N) {
        float s, c;
        sincosf(w[N + i], &s, &c);
        g_cw1[i] = make_float2(c, s);
    }
}

union PU { ull u; float2 f; };
__device__ __forceinline__ float2 padd(float2 a, float2 b) {
    PU ua, ub, r; ua.f = a; ub.f = b;
    asm("add.rn.f32x2 %0,%1,%2;" : "=l"(r.u) : "l"(ua.u), "l"(ub.u));
    return r.f;
}
__device__ __forceinline__ float2 psub(float2 a, float2 b) {
    PU ua, ub, r; ua.f = a; ub.f = b;
    asm("sub.rn.f32x2 %0,%1,%2;" : "=l"(r.u) : "l"(ua.u), "l"(ub.u));
    return r.f;
}
__device__ __forceinline__ float2 pmul(float2 a, float2 b) {
    PU ua, ub, r; ua.f = a; ub.f = b;
    asm("mul.rn.f32x2 %0,%1,%2;" : "=l"(r.u) : "l"(ua.u), "l"(ub.u));
    return r.f;
}
__device__ __forceinline__ float2 pmi(float2 z) {      // z * (-i)
    return make_float2(z.y, -z.x);
}
__device__ __forceinline__ float2 cmul(float2 a, float2 b) {
    return make_float2(a.x * b.x - a.y * b.y, a.x * b.y + a.y * b.x);
}

// DFT4 (forward, W4 = -i)
#define DFT4P(x0,x1,x2,x3, X0,X1,X2,X3) do {                                   \
    float2 t_ = padd(x0, x2), u_ = psub(x0, x2);                               \
    float2 v_ = padd(x1, x3), s_ = psub(x1, x3);                               \
    float2 ms_ = pmi(s_);                                                      \
    X0 = padd(t_, v_); X1 = padd(u_, ms_);                                     \
    X2 = psub(t_, v_); X3 = psub(u_, ms_);                                     \
} while (0)

// DFT8 second half given first-layer outputs
#define DFT8_TAIL(t0,t1,t2,t3,s0,s1,s2,s3, X0,X1,X2,X3,X4,X5,X6,X7, C707P) do {\
    float2 E0 = padd(t0, t2), E2 = psub(t0, t2);                               \
    float2 m3 = pmi(t3);                                                       \
    float2 E1 = padd(t1, m3), E3 = psub(t1, m3);                               \
    float2 O0 = padd(s0, s2), O2 = psub(s0, s2);                               \
    float2 n3 = pmi(s3);                                                       \
    float2 O1 = padd(s1, n3), O3 = psub(s1, n3);                               \
    float2 W1O = pmul(C707P, padd(O1, pmi(O1)));                               \
    float2 W2O = pmi(O2);                                                      \
    float2 W3O = pmul(C707P, psub(pmi(O3), O3));                               \
    X0 = padd(E0, O0);  X4 = psub(E0, O0);                                     \
    X1 = padd(E1, W1O); X5 = psub(E1, W1O);                                    \
    X2 = padd(E2, W2O); X6 = psub(E2, W2O);                                    \
    X3 = padd(E3, W3O); X7 = psub(E3, W3O);                                    \
} while (0)

__device__ __forceinline__ void dft8(const float2* x, float2* X, float2 C707P) {
    float2 u0 = padd(x[0], x[4]), u1 = psub(x[0], x[4]);
    float2 u2 = padd(x[2], x[6]), u3 = psub(x[2], x[6]);
    float2 v0 = padd(x[1], x[5]), v1 = psub(x[1], x[5]);
    float2 v2 = padd(x[3], x[7]), v3 = psub(x[3], x[7]);
    DFT8_TAIL(u0, u1, u2, u3, v0, v1, v2, v3,
              X[0], X[1], X[2], X[3], X[4], X[5], X[6], X[7], C707P);
}

// DFT16: G[k1] = sum_p g[p] W16^{p k1}, p = b + 4a, k1 = c + 4d.
__device__ __forceinline__ void dft16(float2* g, float2* O) {
#pragma unroll
    for (int b = 0; b < 4; b++) {
        float2 X0, X1, X2, X3;
        DFT4P(g[b], g[b + 4], g[b + 8], g[b + 12], X0, X1, X2, X3);
        g[b] = X0; g[b + 4] = X1; g[b + 8] = X2; g[b + 12] = X3;
    }
    const float2 W1 = make_float2(0.92387953251128674f, -0.38268343236508978f);
    const float2 W2 = make_float2(C707, -C707);
    const float2 W3 = make_float2(0.38268343236508978f, -0.92387953251128674f);
    const float2 W6 = make_float2(-C707, -C707);
    const float2 W9 = make_float2(-0.92387953251128674f, 0.38268343236508978f);
    g[5]  = cmul(g[5],  W1); g[6]  = cmul(g[6],  W2); g[7]  = cmul(g[7],  W3);
    g[9]  = cmul(g[9],  W2); g[10] = pmi(g[10]);      g[11] = cmul(g[11], W6);
    g[13] = cmul(g[13], W3); g[14] = cmul(g[14], W6); g[15] = cmul(g[15], W9);
#pragma unroll
    for (int c = 0; c < 4; c++) {
        float2 X0, X1, X2, X3;
        DFT4P(g[4 * c], g[4 * c + 1], g[4 * c + 2], g[4 * c + 3], X0, X1, X2, X3);
        O[c] = X0; O[c + 4] = X1; O[c + 8] = X2; O[c + 12] = X3;
    }
}

// O[k] *= w1^k, k=1..15 (shallow power tree) — used in phase 1 only
__device__ __forceinline__ void twiddle15(float2* O, float2 w1) {
    float2 w2 = cmul(w1, w1), w3 = cmul(w1, w2), w4 = cmul(w2, w2);
    float2 w5 = cmul(w1, w4), w6 = cmul(w2, w4), w7 = cmul(w3, w4);
    float2 w8 = cmul(w4, w4);
    O[1] = cmul(O[1], w1);  O[2] = cmul(O[2], w2);  O[3] = cmul(O[3], w3);
    O[4] = cmul(O[4], w4);  O[5] = cmul(O[5], w5);  O[6] = cmul(O[6], w6);
    O[7] = cmul(O[7], w7);  O[8] = cmul(O[8], w8);
    O[9]  = cmul(O[9],  cmul(w1, w8)); O[10] = cmul(O[10], cmul(w2, w8));
    O[11] = cmul(O[11], cmul(w3, w8)); O[12] = cmul(O[12], cmul(w4, w8));
    O[13] = cmul(O[13], cmul(w5, w8)); O[14] = cmul(O[14], cmul(w6, w8));
    O[15] = cmul(O[15], cmul(w7, w8));
}

__global__ __launch_bounds__(NT, 10) void vpc_main(const float* __restrict__ x,
                                                   const float* __restrict__ w,
                                                   float* __restrict__ out) {
    __shared__ __align__(16) float2 sA[2304];
    __shared__ __align__(16) float2 sTW[128];   // T[v][al] = W128^{v*al}

    const int q = threadIdx.x;      // 0..127
    const int row = blockIdx.x;
    const float* xrow = x + (size_t)row * N;
    const float2 C707P = make_float2(C707, C707);

    // ---- Phase-2a twiddle table (8 rows x 16) ----
    {
        int v = q >> 4, al = q & 15;
        float s, c;
        __sincosf((-(float)CUDART_PI / 64.0f) * (float)(v * al), &s, &c);
        sTW[q] = make_float2(c, s);
    }

    // ---- Phase 1: head (z = exp(i(x+w0)), pair butterfly) + local DFT16 over p
    const int qb = q & ~1;
    const bool odd = (q & 1);
    float2 g[16], O[16];
#pragma unroll
    for (int p = 0; p < 16; p++) {
        int nb = 128 * p + qb;
        float2 xv = *(const float2*)(xrow + nb);
        float2 wv = __ldg((const float2*)(w + nb));
        float s0, c0, s1, c1;
        __sincosf(xv.x + wv.x, &s0, &c0);
        __sincosf(xv.y + wv.y, &s1, &c1);
        g[p] = odd ? make_float2(c0 - c1, s0 - s1)
                   : make_float2(c0 + c1, s0 + s1);
    }
    dft16(g, O);
    float2 wq;
    __sincosf((-(float)CUDART_PI / 1024.0f) * (float)q, &wq.y, &wq.x);  // W2048^q
    twiddle15(O, wq);
    // layout A: addr = 17*q + k1
#pragma unroll
    for (int k = 0; k < 16; k++) sA[17 * q + k] = O[k];
    __syncthreads();

    // ---- Phase 2a: DFT16 over u (q = 8u+v) for fixed (k1, v) ----
    const int k1 = q & 15, vg = q >> 4;
#pragma unroll
    for (int u = 0; u < 16; u++) g[u] = sA[17 * (8 * u + vg) + k1];
    __syncthreads();
    dft16(g, O);
    // twiddle W128^{v*al} from table (8x LDS.128, broadcast within vg groups)
    {
        const float4* Trow = (const float4*)(sTW + 16 * vg);
#pragma unroll
        for (int h = 0; h < 8; h++) {
            float4 tv = Trow[h];
            if (h > 0) O[2 * h] = cmul(O[2 * h], make_float2(tv.x, tv.y));
            O[2 * h + 1] = cmul(O[2 * h + 1], make_float2(tv.z, tv.w));
        }
    }
    // layout B: addr = 288*v + 18*alpha + k1
#pragma unroll
    for (int al = 0; al < 16; al++) sA[288 * vg + 18 * al + k1] = O[al];
    __syncthreads();

    // ---- Phase 2b: DFT8 over v + layer1 + tail, all in registers ----
    const int al2 = q >> 3;
    const int k1e = 2 * (q & 7);
    float2 Zi[8], Qi[8];
#pragma unroll
    for (int v2 = 0; v2 < 8; v2++) {
        float4 P4 = *(const float4*)(sA + 288 * v2 + 18 * al2 + k1e);
        Zi[v2] = make_float2(P4.x, P4.y);
        Qi[v2] = make_float2(P4.z, P4.w);
    }
    float2 A[8], B[8];
    dft8(Zi, A, C707P);   // A[beta] = Z[2q + 256 beta]
    dft8(Qi, B, C707P);   // B[beta] = Z[2q+1 + 256 beta]

    // layer 1 (×exp(i w1)) + pair butterfly
#pragma unroll
    for (int b2 = 0; b2 < 8; b2++) {
        float4 cw = __ldg(&((const float4*)g_cw1)[q + 128 * b2]);
        float2 ue = cmul(A[b2], make_float2(cw.x, cw.y));
        float2 uo = cmul(B[b2], make_float2(cw.z, cw.w));
        A[b2] = padd(ue, uo);
        B[b2] = psub(ue, uo);
    }
    float2 Pj[8], Mj[8];
    dft8(A, Pj, C707P);
    dft8(B, Mj, C707P);

    // cos/sin(pi*k/1024), k=0..9
    const float CK[NCLS] = {1.0f, 0.99999529380957619f, 0.99998117528260111f,
                            0.99995764455196390f, 0.99992470183914450f,
                            0.99988234745421256f, 0.99983058179582340f,
                            0.99976940535121528f, 0.99969881869620425f,
                            0.99961882249517864f};
    const float SK[NCLS] = {0.0f, 0.0030679567629659761f, 0.0061358846491544753f,
                            0.0092037547820598194f, 0.012271538285719925f,
                            0.015339206284988100f, 0.018406729905804820f,
                            0.021474080275469508f, 0.024541228522912288f,
                            0.027608145778965740f};

    // X_k partial = wt^k (P[j] + (CK,-SK)·M[j]),  j=k&7,  wt = W1024^q = wq^2
    float rv[20];
    {
        float2 wt = cmul(wq, wq);
        float2 wk = make_float2(1.0f, 0.0f);
#pragma unroll
        for (int k = 0; k < NCLS; k++) {
            int j = k & 7;
            float2 cM = make_float2(CK[k] * Mj[j].x + SK[k] * Mj[j].y,
                                    CK[k] * Mj[j].y - SK[k] * Mj[j].x);
            float2 inner = padd(Pj[j], cM);
            float2 ac = cmul(wk, inner);
            rv[2 * k] = ac.x; rv[2 * k + 1] = ac.y;
            wk = cmul(wk, wt);
        }
    }

    // ---- Value-splitting warp reduction: 20 scalars -> 5 per lane ----
    const int lane = q & 31;
    float h1[10];
    {
        const bool hi = (lane & 16);
#pragma unroll
        for (int j = 0; j < 10; j++) {
            float send = hi ? rv[j] : rv[j + 10];
            float recv = __shfl_xor_sync(0xFFFFFFFFu, send, 16);
            h1[j] = (hi ? rv[j + 10] : rv[j]) + recv;
        }
    }
    float h2[5];
    {
        const bool hi = (lane & 8);
#pragma unroll
        for (int j = 0; j < 5; j++) {
            float send = hi ? h1[j] : h1[j + 5];
            float recv = __shfl_xor_sync(0xFFFFFFFFu, send, 8);
            h2[j] = (hi ? h1[j + 5] : h1[j]) + recv;
        }
    }
#pragma unroll
    for (int off = 4; off > 0; off >>= 1) {
#pragma unroll
        for (int j = 0; j < 5; j++)
            h2[j] += __shfl_xor_sync(0xFFFFFFFFu, h2[j], off);
    }

    // ---- Cross-warp reduction (4 warps) via sA ----
    __syncthreads();
    float* red    = (float*)sA;
    float* logits = (float*)sA + 4 * 20;
    const int wrp = q >> 5;
    if ((lane & 7) == 0) {
        int base = wrp * 20 + ((lane >> 3) & 3) * 5;
#pragma unroll
        for (int j = 0; j < 5; j++) red[base + j] = h2[j];
    }
    __syncthreads();

    if (q < NCLS) {
        float re = 0.f, im = 0.f;
#pragma unroll
        for (int wq2 = 0; wq2 < NT / 32; wq2++) {
            re += red[wq2 * 20 + 2 * q];
            im += red[wq2 * 20 + 2 * q + 1];
        }
        float r2v = re * re + im * im;
        // sin(atan2(im,re)) = im/|z|; dropped norms positive -> phases unchanged
        logits[q] = (r2v > 0.f) ? 5.0f * im * rsqrtf(r2v) : 0.0f;
    }
    __syncthreads();

    if (q < NCLS) {
        float m = -1e30f;
#pragma unroll
        for (int k = 0; k < NCLS; k++) m = fmaxf(m, logits[k]);
        float sum = 0.f;
#pragma unroll
        for (int k = 0; k < NCLS; k++) sum += __expf(logits[k] - m);
        out[(size_t)row * NCLS + q] = __expf(logits[q] - m) / sum;
    }
}

extern "C" void kernel_launch(void* const* d_in, const int* in_sizes, int n_in,
                              void* d_out, int out_size) {
    const float* x = (const float*)d_in[0];     // (8192, 2048) fp32
    const float* w = (const float*)d_in[1];     // (4096,) fp32
    float* out = (float*)d_out;                 // (8192, 10) fp32

    vpc_init<<<(N + 255) / 256, 256>>>(w);
    vpc_main<<<8192, NT>>>(x, w, out);
}

// round 15
// speedup vs baseline: 1.3877x; 1.3877x over previous
#include <cuda_runtime.h>
#include <math_constants.h>

#define N     2048
#define NT    128
#define NCLS  10
#define C707  0.70710678118654752440f

typedef unsigned long long ull;

__device__ float2 g_cw1[N];   // exp(i*w1[n]), row-invariant

__global__ void vpc_init(const float* __restrict__ w) {
    int i = blockIdx.x * blockDim.x + threadIdx.x;
    if (i < N) {
        float s, c;
        sincosf(w[N + i], &s, &c);
        g_cw1[i] = make_float2(c, s);
    }
}

union PU { ull u; float2 f; };
__device__ __forceinline__ float2 padd(float2 a, float2 b) {
    PU ua, ub, r; ua.f = a; ub.f = b;
    asm("add.rn.f32x2 %0,%1,%2;" : "=l"(r.u) : "l"(ua.u), "l"(ub.u));
    return r.f;
}
__device__ __forceinline__ float2 psub(float2 a, float2 b) {
    PU ua, ub, r; ua.f = a; ub.f = b;
    asm("sub.rn.f32x2 %0,%1,%2;" : "=l"(r.u) : "l"(ua.u), "l"(ub.u));
    return r.f;
}
__device__ __forceinline__ float2 pmul(float2 a, float2 b) {
    PU ua, ub, r; ua.f = a; ub.f = b;
    asm("mul.rn.f32x2 %0,%1,%2;" : "=l"(r.u) : "l"(ua.u), "l"(ub.u));
    return r.f;
}
__device__ __forceinline__ float2 pmi(float2 z) {      // z * (-i)
    return make_float2(z.y, -z.x);
}
__device__ __forceinline__ float2 cmul(float2 a, float2 b) {
    return make_float2(a.x * b.x - a.y * b.y, a.x * b.y + a.y * b.x);
}

// DFT4 (forward, W4 = -i)
#define DFT4P(x0,x1,x2,x3, X0,X1,X2,X3) do {                                   \
    float2 t_ = padd(x0, x2), u_ = psub(x0, x2);                               \
    float2 v_ = padd(x1, x3), s_ = psub(x1, x3);                               \
    float2 ms_ = pmi(s_);                                                      \
    X0 = padd(t_, v_); X1 = padd(u_, ms_);                                     \
    X2 = psub(t_, v_); X3 = psub(u_, ms_);                                     \
} while (0)

// DFT8 second half given first-layer outputs
#define DFT8_TAIL(t0,t1,t2,t3,s0,s1,s2,s3, X0,X1,X2,X3,X4,X5,X6,X7, C707P) do {\
    float2 E0 = padd(t0, t2), E2 = psub(t0, t2);                               \
    float2 m3 = pmi(t3);                                                       \
    float2 E1 = padd(t1, m3), E3 = psub(t1, m3);                               \
    float2 O0 = padd(s0, s2), O2 = psub(s0, s2);                               \
    float2 n3 = pmi(s3);                                                       \
    float2 O1 = padd(s1, n3), O3 = psub(s1, n3);                               \
    float2 W1O = pmul(C707P, padd(O1, pmi(O1)));                               \
    float2 W2O = pmi(O2);                                                      \
    float2 W3O = pmul(C707P, psub(pmi(O3), O3));                               \
    X0 = padd(E0, O0);  X4 = psub(E0, O0);                                     \
    X1 = padd(E1, W1O); X5 = psub(E1, W1O);                                    \
    X2 = padd(E2, W2O); X6 = psub(E2, W2O);                                    \
    X3 = padd(E3, W3O); X7 = psub(E3, W3O);                                    \
} while (0)

__device__ __forceinline__ void dft8(const float2* x, float2* X, float2 C707P) {
    float2 u0 = padd(x[0], x[4]), u1 = psub(x[0], x[4]);
    float2 u2 = padd(x[2], x[6]), u3 = psub(x[2], x[6]);
    float2 v0 = padd(x[1], x[5]), v1 = psub(x[1], x[5]);
    float2 v2 = padd(x[3], x[7]), v3 = psub(x[3], x[7]);
    DFT8_TAIL(u0, u1, u2, u3, v0, v1, v2, v3,
              X[0], X[1], X[2], X[3], X[4], X[5], X[6], X[7], C707P);
}

// DFT16: G[k1] = sum_p g[p] W16^{p k1}, p = b + 4a, k1 = c + 4d.
__device__ __forceinline__ void dft16(float2* g, float2* O) {
#pragma unroll
    for (int b = 0; b < 4; b++) {
        float2 X0, X1, X2, X3;
        DFT4P(g[b], g[b + 4], g[b + 8], g[b + 12], X0, X1, X2, X3);
        g[b] = X0; g[b + 4] = X1; g[b + 8] = X2; g[b + 12] = X3;
    }
    const float2 W1 = make_float2(0.92387953251128674f, -0.38268343236508978f);
    const float2 W2 = make_float2(C707, -C707);
    const float2 W3 = make_float2(0.38268343236508978f, -0.92387953251128674f);
    const float2 W6 = make_float2(-C707, -C707);
    const float2 W9 = make_float2(-0.92387953251128674f, 0.38268343236508978f);
    g[5]  = cmul(g[5],  W1); g[6]  = cmul(g[6],  W2); g[7]  = cmul(g[7],  W3);
    g[9]  = cmul(g[9],  W2); g[10] = pmi(g[10]);      g[11] = cmul(g[11], W6);
    g[13] = cmul(g[13], W3); g[14] = cmul(g[14], W6); g[15] = cmul(g[15], W9);
#pragma unroll
    for (int c = 0; c < 4; c++) {
        float2 X0, X1, X2, X3;
        DFT4P(g[4 * c], g[4 * c + 1], g[4 * c + 2], g[4 * c + 3], X0, X1, X2, X3);
        O[c] = X0; O[c + 4] = X1; O[c + 8] = X2; O[c + 12] = X3;
    }
}

// O[k] *= w1^k, k=1..15 (shallow power tree)
__device__ __forceinline__ void twiddle15(float2* O, float2 w1) {
    float2 w2 = cmul(w1, w1), w3 = cmul(w1, w2), w4 = cmul(w2, w2);
    float2 w5 = cmul(w1, w4), w6 = cmul(w2, w4), w7 = cmul(w3, w4);
    float2 w8 = cmul(w4, w4);
    O[1] = cmul(O[1], w1);  O[2] = cmul(O[2], w2);  O[3] = cmul(O[3], w3);
    O[4] = cmul(O[4], w4);  O[5] = cmul(O[5], w5);  O[6] = cmul(O[6], w6);
    O[7] = cmul(O[7], w7);  O[8] = cmul(O[8], w8);
    O[9]  = cmul(O[9],  cmul(w1, w8)); O[10] = cmul(O[10], cmul(w2, w8));
    O[11] = cmul(O[11], cmul(w3, w8)); O[12] = cmul(O[12], cmul(w4, w8));
    O[13] = cmul(O[13], cmul(w5, w8)); O[14] = cmul(O[14], cmul(w6, w8));
    O[15] = cmul(O[15], cmul(w7, w8));
}

// n = 128 p + q decomposition; k = k1 + 16 k2; k2 = alpha + 16 beta.
__global__ __launch_bounds__(NT, 9) void vpc_main(const float* __restrict__ x,
                                                  const float* __restrict__ w,
                                                  float* __restrict__ out) {
    __shared__ __align__(16) float2 sA[2304];

    const int q = threadIdx.x;      // 0..127
    const int row = blockIdx.x;
    const float* xrow = x + (size_t)row * N;
    const float2 C707P = make_float2(C707, C707);

    // ---- Phase 1: head (z = exp(i(x+w0)), pair butterfly) + local DFT16 over p
    const int qb = q & ~1;
    const bool odd = (q & 1);
    float2 g[16], O[16];
#pragma unroll
    for (int p = 0; p < 16; p++) {
        int nb = 128 * p + qb;
        float2 xv = *(const float2*)(xrow + nb);
        float2 wv = __ldg((const float2*)(w + nb));
        float s0, c0, s1, c1;
        __sincosf(xv.x + wv.x, &s0, &c0);
        __sincosf(xv.y + wv.y, &s1, &c1);
        g[p] = odd ? make_float2(c0 - c1, s0 - s1)
                   : make_float2(c0 + c1, s0 + s1);
    }
    dft16(g, O);
    {
        float2 wq;
        __sincosf((-(float)CUDART_PI / 1024.0f) * (float)q, &wq.y, &wq.x);  // W2048^q
        twiddle15(O, wq);
    }
    // layout A: addr = 17*q + k1
#pragma unroll
    for (int k = 0; k < 16; k++) sA[17 * q + k] = O[k];
    __syncthreads();

    // ---- Phase 2a: DFT16 over u (q = 8u+v) for fixed (k1, v) ----
    const int k1 = q & 15, vg = q >> 4;
#pragma unroll
    for (int u = 0; u < 16; u++) g[u] = sA[17 * (8 * u + vg) + k1];
    __syncthreads();
    dft16(g, O);
    {
        float2 wv2;
        __sincosf((-(float)CUDART_PI / 64.0f) * (float)vg, &wv2.y, &wv2.x); // W128^v
        twiddle15(O, wv2);
    }
    // layout B: addr = 288*v + 18*alpha + k1
#pragma unroll
    for (int al = 0; al < 16; al++) sA[288 * vg + 18 * al + k1] = O[al];
    __syncthreads();

    // ---- Phase 2b: DFT8 over v + layer1 + tail, all in registers ----
    const int al2 = q >> 3;
    const int k1e = 2 * (q & 7);
    float2 Zi[8], Qi[8];
#pragma unroll
    for (int v2 = 0; v2 < 8; v2++) {
        float4 P4 = *(const float4*)(sA + 288 * v2 + 18 * al2 + k1e);
        Zi[v2] = make_float2(P4.x, P4.y);
        Qi[v2] = make_float2(P4.z, P4.w);
    }
    float2 A[8], B[8];
    dft8(Zi, A, C707P);   // A[beta] = Z[2q + 256 beta]
    dft8(Qi, B, C707P);   // B[beta] = Z[2q+1 + 256 beta]

    // layer 1 (×exp(i w1)) + pair butterfly
#pragma unroll
    for (int b2 = 0; b2 < 8; b2++) {
        float4 cw = __ldg(&((const float4*)g_cw1)[q + 128 * b2]);
        float2 ue = cmul(A[b2], make_float2(cw.x, cw.y));
        float2 uo = cmul(B[b2], make_float2(cw.z, cw.w));
        A[b2] = padd(ue, uo);
        B[b2] = psub(ue, uo);
    }
    float2 Pj[8], Mj[8];
    dft8(A, Pj, C707P);
    dft8(B, Mj, C707P);

    // cos/sin(pi*k/1024), k=0..9
    const float CK[NCLS] = {1.0f, 0.99999529380957619f, 0.99998117528260111f,
                            0.99995764455196390f, 0.99992470183914450f,
                            0.99988234745421256f, 0.99983058179582340f,
                            0.99976940535121528f, 0.99969881869620425f,
                            0.99961882249517864f};
    const float SK[NCLS] = {0.0f, 0.0030679567629659761f, 0.0061358846491544753f,
                            0.0092037547820598194f, 0.012271538285719925f,
                            0.015339206284988100f, 0.018406729905804820f,
                            0.021474080275469508f, 0.024541228522912288f,
                            0.027608145778965740f};

    // X_k partial = wt^k (P[j] + (CK,-SK)·M[j]),  j=k&7,  wt = W1024^q
    float rv[20];
    {
        float2 wt;
        __sincosf((-(float)CUDART_PI / 512.0f) * (float)q, &wt.y, &wt.x);
        float2 wk = make_float2(1.0f, 0.0f);
#pragma unroll
        for (int k = 0; k < NCLS; k++) {
            int j = k & 7;
            float2 cM = make_float2(CK[k] * Mj[j].x + SK[k] * Mj[j].y,
                                    CK[k] * Mj[j].y - SK[k] * Mj[j].x);
            float2 inner = padd(Pj[j], cM);
            float2 ac = cmul(wk, inner);
            rv[2 * k] = ac.x; rv[2 * k + 1] = ac.y;
            wk = cmul(wk, wt);
        }
    }

    // ---- Value-splitting warp reduction: 20 scalars -> 5 per lane ----
    const int lane = q & 31;
    float h1[10];
    {
        const bool hi = (lane & 16);
#pragma unroll
        for (int j = 0; j < 10; j++) {
            float send = hi ? rv[j] : rv[j + 10];
            float recv = __shfl_xor_sync(0xFFFFFFFFu, send, 16);
            h1[j] = (hi ? rv[j + 10] : rv[j]) + recv;
        }
    }
    float h2[5];
    {
        const bool hi = (lane & 8);
#pragma unroll
        for (int j = 0; j < 5; j++) {
            float send = hi ? h1[j] : h1[j + 5];
            float recv = __shfl_xor_sync(0xFFFFFFFFu, send, 8);
            h2[j] = (hi ? h1[j + 5] : h1[j]) + recv;
        }
    }
#pragma unroll
    for (int off = 4; off > 0; off >>= 1) {
#pragma unroll
        for (int j = 0; j < 5; j++)
            h2[j] += __shfl_xor_sync(0xFFFFFFFFu, h2[j], off);
    }

    // ---- Cross-warp reduction (4 warps) via sA ----
    __syncthreads();                    // all phase-2b shared reads done
    float* red    = (float*)sA;         // 4 warps * 20 scalars
    float* logits = (float*)sA + 4 * 20;
    const int wrp = q >> 5;
    if ((lane & 7) == 0) {
        int base = wrp * 20 + ((lane >> 3) & 3) * 5;
#pragma unroll
        for (int j = 0; j < 5; j++) red[base + j] = h2[j];
    }
    __syncthreads();

    if (q < NCLS) {
        float re = 0.f, im = 0.f;
#pragma unroll
        for (int wq2 = 0; wq2 < NT / 32; wq2++) {
            re += red[wq2 * 20 + 2 * q];
            im += red[wq2 * 20 + 2 * q + 1];
        }
        float r2v = re * re + im * im;
        // sin(atan2(im,re)) = im/|z|; dropped norms positive -> phases unchanged
        logits[q] = (r2v > 0.f) ? 5.0f * im * rsqrtf(r2v) : 0.0f;
    }
    __syncthreads();

    if (q < NCLS) {
        float m = -1e30f;
#pragma unroll
        for (int k = 0; k < NCLS; k++) m = fmaxf(m, logits[k]);
        float sum = 0.f;
#pragma unroll
        for (int k = 0; k < NCLS; k++) sum += __expf(logits[k] - m);
        out[(size_t)row * NCLS + q] = __expf(logits[q] - m) / sum;
    }
}

extern "C" void kernel_launch(void* const* d_in, const int* in_sizes, int n_in,
                              void* d_out, int out_size) {
    const float* x = (const float*)d_in[0];     // (8192, 2048) fp32
    const float* w = (const float*)d_in[1];     // (4096,) fp32
    float* out = (float*)d_out;                 // (8192, 10) fp32

    vpc_init<<<(N + 255) / 256, 256>>>(w);
    vpc_main<<<8192, NT>>>(x, w, out);
}

// round 16
// speedup vs baseline: 1.4997x; 1.0807x over previous
#include <cuda_runtime.h>
#include <math_constants.h>

#define N     2048
#define NT    128
#define NCLS  10
#define C707  0.70710678118654752440f

typedef unsigned long long ull;

__device__ float2 g_cw1[N];   // exp(i*w1[n]), row-invariant

__global__ void vpc_init(const float* __restrict__ w) {
    int i = blockIdx.x * blockDim.x + threadIdx.x;
    if (i < N) {
        float s, c;
        sincosf(w[N + i], &s, &c);
        g_cw1[i] = make_float2(c, s);
    }
}

union PU { ull u; float2 f; };
__device__ __forceinline__ float2 padd(float2 a, float2 b) {
    PU ua, ub, r; ua.f = a; ub.f = b;
    asm("add.rn.f32x2 %0,%1,%2;" : "=l"(r.u) : "l"(ua.u), "l"(ub.u));
    return r.f;
}
__device__ __forceinline__ float2 psub(float2 a, float2 b) {
    PU ua, ub, r; ua.f = a; ub.f = b;
    asm("sub.rn.f32x2 %0,%1,%2;" : "=l"(r.u) : "l"(ua.u), "l"(ub.u));
    return r.f;
}
__device__ __forceinline__ float2 pmul(float2 a, float2 b) {
    PU ua, ub, r; ua.f = a; ub.f = b;
    asm("mul.rn.f32x2 %0,%1,%2;" : "=l"(r.u) : "l"(ua.u), "l"(ub.u));
    return r.f;
}
__device__ __forceinline__ float2 pmi(float2 z) {      // z * (-i)
    return make_float2(z.y, -z.x);
}
__device__ __forceinline__ float2 cmul(float2 a, float2 b) {
    return make_float2(a.x * b.x - a.y * b.y, a.x * b.y + a.y * b.x);
}

// DFT4 (forward, W4 = -i)
#define DFT4P(x0,x1,x2,x3, X0,X1,X2,X3) do {                                   \
    float2 t_ = padd(x0, x2), u_ = psub(x0, x2);                               \
    float2 v_ = padd(x1, x3), s_ = psub(x1, x3);                               \
    float2 ms_ = pmi(s_);                                                      \
    X0 = padd(t_, v_); X1 = padd(u_, ms_);                                     \
    X2 = psub(t_, v_); X3 = psub(u_, ms_);                                     \
} while (0)

// DFT8 second half given first-layer outputs
#define DFT8_TAIL(t0,t1,t2,t3,s0,s1,s2,s3, X0,X1,X2,X3,X4,X5,X6,X7, C707P) do {\
    float2 E0 = padd(t0, t2), E2 = psub(t0, t2);                               \
    float2 m3 = pmi(t3);                                                       \
    float2 E1 = padd(t1, m3), E3 = psub(t1, m3);                               \
    float2 O0 = padd(s0, s2), O2 = psub(s0, s2);                               \
    float2 n3 = pmi(s3);                                                       \
    float2 O1 = padd(s1, n3), O3 = psub(s1, n3);                               \
    float2 W1O = pmul(C707P, padd(O1, pmi(O1)));                               \
    float2 W2O = pmi(O2);                                                      \
    float2 W3O = pmul(C707P, psub(pmi(O3), O3));                               \
    X0 = padd(E0, O0);  X4 = psub(E0, O0);                                     \
    X1 = padd(E1, W1O); X5 = psub(E1, W1O);                                    \
    X2 = padd(E2, W2O); X6 = psub(E2, W2O);                                    \
    X3 = padd(E3, W3O); X7 = psub(E3, W3O);                                    \
} while (0)

__device__ __forceinline__ void dft8(const float2* x, float2* X, float2 C707P) {
    float2 u0 = padd(x[0], x[4]), u1 = psub(x[0], x[4]);
    float2 u2 = padd(x[2], x[6]), u3 = psub(x[2], x[6]);
    float2 v0 = padd(x[1], x[5]), v1 = psub(x[1], x[5]);
    float2 v2 = padd(x[3], x[7]), v3 = psub(x[3], x[7]);
    DFT8_TAIL(u0, u1, u2, u3, v0, v1, v2, v3,
              X[0], X[1], X[2], X[3], X[4], X[5], X[6], X[7], C707P);
}

// DFT16: G[k1] = sum_p g[p] W16^{p k1}, p = b + 4a, k1 = c + 4d.
__device__ __forceinline__ void dft16(float2* g, float2* O) {
#pragma unroll
    for (int b = 0; b < 4; b++) {
        float2 X0, X1, X2, X3;
        DFT4P(g[b], g[b + 4], g[b + 8], g[b + 12], X0, X1, X2, X3);
        g[b] = X0; g[b + 4] = X1; g[b + 8] = X2; g[b + 12] = X3;
    }
    const float2 W1 = make_float2(0.92387953251128674f, -0.38268343236508978f);
    const float2 W2 = make_float2(C707, -C707);
    const float2 W3 = make_float2(0.38268343236508978f, -0.92387953251128674f);
    const float2 W6 = make_float2(-C707, -C707);
    const float2 W9 = make_float2(-0.92387953251128674f, 0.38268343236508978f);
    g[5]  = cmul(g[5],  W1); g[6]  = cmul(g[6],  W2); g[7]  = cmul(g[7],  W3);
    g[9]  = cmul(g[9],  W2); g[10] = pmi(g[10]);      g[11] = cmul(g[11], W6);
    g[13] = cmul(g[13], W3); g[14] = cmul(g[14], W6); g[15] = cmul(g[15], W9);
#pragma unroll
    for (int c = 0; c < 4; c++) {
        float2 X0, X1, X2, X3;
        DFT4P(g[4 * c], g[4 * c + 1], g[4 * c + 2], g[4 * c + 3], X0, X1, X2, X3);
        O[c] = X0; O[c + 4] = X1; O[c + 8] = X2; O[c + 12] = X3;
    }
}

// O[k] *= w1^k, k=1..15 (shallow power tree) — phase 1 only (128 distinct w1)
__device__ __forceinline__ void twiddle15(float2* O, float2 w1) {
    float2 w2 = cmul(w1, w1), w3 = cmul(w1, w2), w4 = cmul(w2, w2);
    float2 w5 = cmul(w1, w4), w6 = cmul(w2, w4), w7 = cmul(w3, w4);
    float2 w8 = cmul(w4, w4);
    O[1] = cmul(O[1], w1);  O[2] = cmul(O[2], w2);  O[3] = cmul(O[3], w3);
    O[4] = cmul(O[4], w4);  O[5] = cmul(O[5], w5);  O[6] = cmul(O[6], w6);
    O[7] = cmul(O[7], w7);  O[8] = cmul(O[8], w8);
    O[9]  = cmul(O[9],  cmul(w1, w8)); O[10] = cmul(O[10], cmul(w2, w8));
    O[11] = cmul(O[11], cmul(w3, w8)); O[12] = cmul(O[12], cmul(w4, w8));
    O[13] = cmul(O[13], cmul(w5, w8)); O[14] = cmul(O[14], cmul(w6, w8));
    O[15] = cmul(O[15], cmul(w7, w8));
}

// n = 128 p + q decomposition; k = k1 + 16 k2; k2 = alpha + 16 beta.
__global__ __launch_bounds__(NT, 9) void vpc_main(const float* __restrict__ x,
                                                  const float* __restrict__ w,
                                                  float* __restrict__ out) {
    __shared__ __align__(16) float2 sA[2304];
    __shared__ float2 sTW[128];     // sTW[16*v + al] = W128^{v*al}

    const int q = threadIdx.x;      // 0..127
    const int row = blockIdx.x;
    const float* xrow = x + (size_t)row * N;
    const float2 C707P = make_float2(C707, C707);

    // ---- Phase-2a twiddle table (8 x 16); 1 sincos/thread, visible after
    //      the phase-1 barrier ----
    {
        int v = q >> 4, al = q & 15;
        float s, c;
        __sincosf((-(float)CUDART_PI / 64.0f) * (float)(v * al), &s, &c);
        sTW[q] = make_float2(c, s);
    }

    // ---- Phase 1: head + local DFT16 over p.
    //      Thread q computes sincos of ITS element (128p+q) only; the pair
    //      butterfly partner values come from lane q^1 via shfl. ----
    const bool odd = (q & 1);
    float2 g[16], O[16];
#pragma unroll
    for (int p = 0; p < 16; p++) {
        int n = 128 * p + q;
        float ang = xrow[n] + __ldg(&w[n]);
        float s0, c0;
        __sincosf(ang, &s0, &c0);
        float c1 = __shfl_xor_sync(0xFFFFFFFFu, c0, 1);
        float s1 = __shfl_xor_sync(0xFFFFFFFFu, s0, 1);
        // even lane: e_q + e_{q+1}; odd lane: e_{q-1} - e_q
        g[p] = odd ? make_float2(c1 - c0, s1 - s0)
                   : make_float2(c0 + c1, s0 + s1);
    }
    dft16(g, O);
    {
        float2 wq;
        __sincosf((-(float)CUDART_PI / 1024.0f) * (float)q, &wq.y, &wq.x);  // W2048^q
        twiddle15(O, wq);
    }
    // layout A: addr = 17*q + k1
#pragma unroll
    for (int k = 0; k < 16; k++) sA[17 * q + k] = O[k];
    __syncthreads();

    // ---- Phase 2a: DFT16 over u (q = 8u+v) for fixed (k1, v) ----
    const int k1 = q & 15, vg = q >> 4;
#pragma unroll
    for (int u = 0; u < 16; u++) g[u] = sA[17 * (8 * u + vg) + k1];
    __syncthreads();
    dft16(g, O);
    // twiddle W128^{v*al} from table: 15 broadcast LDS.64, each feeding one cmul
    {
        const float2* Trow = sTW + 16 * vg;
#pragma unroll
        for (int al = 1; al < 16; al++) O[al] = cmul(O[al], Trow[al]);
    }
    // layout B: addr = 288*v + 18*alpha + k1
#pragma unroll
    for (int al = 0; al < 16; al++) sA[288 * vg + 18 * al + k1] = O[al];
    __syncthreads();

    // ---- Phase 2b: DFT8 over v + layer1 + tail, all in registers ----
    const int al2 = q >> 3;
    const int k1e = 2 * (q & 7);
    float2 Zi[8], Qi[8];
#pragma unroll
    for (int v2 = 0; v2 < 8; v2++) {
        float4 P4 = *(const float4*)(sA + 288 * v2 + 18 * al2 + k1e);
        Zi[v2] = make_float2(P4.x, P4.y);
        Qi[v2] = make_float2(P4.z, P4.w);
    }
    float2 A[8], B[8];
    dft8(Zi, A, C707P);   // A[beta] = Z[2q + 256 beta]
    dft8(Qi, B, C707P);   // B[beta] = Z[2q+1 + 256 beta]

    // layer 1 (×exp(i w1)) + pair butterfly
#pragma unroll
    for (int b2 = 0; b2 < 8; b2++) {
        float4 cw = __ldg(&((const float4*)g_cw1)[q + 128 * b2]);
        float2 ue = cmul(A[b2], make_float2(cw.x, cw.y));
        float2 uo = cmul(B[b2], make_float2(cw.z, cw.w));
        A[b2] = padd(ue, uo);
        B[b2] = psub(ue, uo);
    }
    float2 Pj[8], Mj[8];
    dft8(A, Pj, C707P);
    dft8(B, Mj, C707P);

    // cos/sin(pi*k/1024), k=0..9
    const float CK[NCLS] = {1.0f, 0.99999529380957619f, 0.99998117528260111f,
                            0.99995764455196390f, 0.99992470183914450f,
                            0.99988234745421256f, 0.99983058179582340f,
                            0.99976940535121528f, 0.99969881869620425f,
                            0.99961882249517864f};
    const float SK[NCLS] = {0.0f, 0.0030679567629659761f, 0.0061358846491544753f,
                            0.0092037547820598194f, 0.012271538285719925f,
                            0.015339206284988100f, 0.018406729905804820f,
                            0.021474080275469508f, 0.024541228522912288f,
                            0.027608145778965740f};

    // X_k partial = wt^k (P[j] + (CK,-SK)·M[j]),  j=k&7,  wt = W1024^q
    float rv[20];
    {
        float2 wt;
        __sincosf((-(float)CUDART_PI / 512.0f) * (float)q, &wt.y, &wt.x);
        float2 wk = make_float2(1.0f, 0.0f);
#pragma unroll
        for (int k = 0; k < NCLS; k++) {
            int j = k & 7;
            float2 cM = make_float2(CK[k] * Mj[j].x + SK[k] * Mj[j].y,
                                    CK[k] * Mj[j].y - SK[k] * Mj[j].x);
            float2 inner = padd(Pj[j], cM);
            float2 ac = cmul(wk, inner);
            rv[2 * k] = ac.x; rv[2 * k + 1] = ac.y;
            wk = cmul(wk, wt);
        }
    }

    // ---- Value-splitting warp reduction: 20 scalars -> 5 per lane ----
    const int lane = q & 31;
    float h1[10];
    {
        const bool hi = (lane & 16);
#pragma unroll
        for (int j = 0; j < 10; j++) {
            float send = hi ? rv[j] : rv[j + 10];
            float recv = __shfl_xor_sync(0xFFFFFFFFu, send, 16);
            h1[j] = (hi ? rv[j + 10] : rv[j]) + recv;
        }
    }
    float h2[5];
    {
        const bool hi = (lane & 8);
#pragma unroll
        for (int j = 0; j < 5; j++) {
            float send = hi ? h1[j] : h1[j + 5];
            float recv = __shfl_xor_sync(0xFFFFFFFFu, send, 8);
            h2[j] = (hi ? h1[j + 5] : h1[j]) + recv;
        }
    }
#pragma unroll
    for (int off = 4; off > 0; off >>= 1) {
#pragma unroll
        for (int j = 0; j < 5; j++)
            h2[j] += __shfl_xor_sync(0xFFFFFFFFu, h2[j], off);
    }

    // ---- Cross-warp reduction (4 warps) via sA ----
    __syncthreads();                    // all phase-2b shared reads done
    float* red    = (float*)sA;         // 4 warps * 20 scalars
    float* logits = (float*)sA + 4 * 20;
    const int wrp = q >> 5;
    if ((lane & 7) == 0) {
        int base = wrp * 20 + ((lane >> 3) & 3) * 5;
#pragma unroll
        for (int j = 0; j < 5; j++) red[base + j] = h2[j];
    }
    __syncthreads();

    if (q < NCLS) {
        float re = 0.f, im = 0.f;
#pragma unroll
        for (int wq2 = 0; wq2 < NT / 32; wq2++) {
            re += red[wq2 * 20 + 2 * q];
            im += red[wq2 * 20 + 2 * q + 1];
        }
        float r2v = re * re + im * im;
        // sin(atan2(im,re)) = im/|z|; dropped norms positive -> phases unchanged
        logits[q] = (r2v > 0.f) ? 5.0f * im * rsqrtf(r2v) : 0.0f;
    }
    __syncthreads();

    if (q < NCLS) {
        float m = -1e30f;
#pragma unroll
        for (int k = 0; k < NCLS; k++) m = fmaxf(m, logits[k]);
        float sum = 0.f;
#pragma unroll
        for (int k = 0; k < NCLS; k++) sum += __expf(logits[k] - m);
        out[(size_t)row * NCLS + q] = __expf(logits[q] - m) / sum;
    }
}

extern "C" void kernel_launch(void* const* d_in, const int* in_sizes, int n_in,
                              void* d_out, int out_size) {
    const float* x = (const float*)d_in[0];     // (8192, 2048) fp32
    const float* w = (const float*)d_in[1];     // (4096,) fp32
    float* out = (float*)d_out;                 // (8192, 10) fp32

    vpc_init<<<(N + 255) / 256, 256>>>(w);
    vpc_main<<<8192, NT>>>(x, w, out);
}